// round 1
// baseline (speedup 1.0000x reference)
#include <cuda_runtime.h>

#define IN_DIM  1024
#define OUT_DIM 512
#define B_DIM   128
#define IC      64      // input-dim chunk staged in smem
#define OT      16      // output tile per block
#define BT      16      // batch tile per block

// Precomputed W_eff * 2*log2(e), so the hot loop does exp2 directly.
__device__ float g_w2[OUT_DIM * IN_DIM];

__device__ __forceinline__ float ex2_approx(float x) {
    float y;
    asm("ex2.approx.f32 %0, %1;" : "=f"(y) : "f"(x));
    return y;
}
__device__ __forceinline__ float rcp_approx(float x) {
    float y;
    asm("rcp.approx.f32 %0, %1;" : "=f"(y) : "f"(x));
    return y;
}

// Kernel 1: W_eff[o,i] = softmax(theta[o,i,:]) . {0, W, tanh(W), sin(W)},
// scaled by 2*log2(e). 512K elements, negligible cost.
__global__ void weff_kernel(const float* __restrict__ W,
                            const float* __restrict__ theta) {
    int idx = blockIdx.x * blockDim.x + threadIdx.x;
    if (idx >= OUT_DIM * IN_DIM) return;
    float4 t = reinterpret_cast<const float4*>(theta)[idx];
    float m = fmaxf(fmaxf(t.x, t.y), fmaxf(t.z, t.w));
    float e0 = expf(t.x - m);
    float e1 = expf(t.y - m);
    float e2 = expf(t.z - m);
    float e3 = expf(t.w - m);
    float inv = 1.0f / (e0 + e1 + e2 + e3);
    float w = W[idx];
    float weff = (e1 * w + e2 * tanhf(w) + e3 * sinf(w)) * inv;
    g_w2[idx] = weff * 2.8853900817779268f;   // 2 * log2(e)
}

// Kernel 2: y[b,o] = bias[o] + sum_i tanh(x[b,i] * W_eff[o,i])
// tanh(z) = 1 - 2/(e^{2z}+1) = -2 * (rcp(ex2(x*w2)+1) - 0.5)
__global__ __launch_bounds__(OT * BT)
void fbn_main_kernel(const float* __restrict__ x,
                     const float* __restrict__ bias,
                     float* __restrict__ out) {
    __shared__ float xs[BT][IC + 1];   // +1 pad: kill bank conflicts
    __shared__ float ws[OT][IC + 1];

    const int tx = threadIdx.x;            // o within tile
    const int ty = threadIdx.y;            // b within tile
    const int o0 = blockIdx.x * OT;
    const int b0 = blockIdx.y * BT;
    const int tid = ty * OT + tx;

    float acc0 = 0.0f, acc1 = 0.0f;

    for (int c = 0; c < IN_DIM; c += IC) {
        __syncthreads();
        // Stage tiles: 16 rows x 64 cols each, coalesced.
        #pragma unroll
        for (int idx = tid; idx < BT * IC; idx += OT * BT) {
            int r = idx / IC;
            int col = idx - r * IC;
            xs[r][col] = x[(b0 + r) * IN_DIM + c + col];
            ws[r][col] = g_w2[(o0 + r) * IN_DIM + c + col];
        }
        __syncthreads();

        #pragma unroll
        for (int i = 0; i < IC; i += 2) {
            float t0 = xs[ty][i]     * ws[tx][i];
            float t1 = xs[ty][i + 1] * ws[tx][i + 1];
            float r0 = rcp_approx(ex2_approx(t0) + 1.0f);
            float r1 = rcp_approx(ex2_approx(t1) + 1.0f);
            acc0 += (r0 - 0.5f);
            acc1 += (r1 - 0.5f);
        }
    }

    // sum tanh = -2 * sum(r - 0.5)
    out[(b0 + ty) * OUT_DIM + (o0 + tx)] =
        bias[o0 + tx] - 2.0f * (acc0 + acc1);
}

extern "C" void kernel_launch(void* const* d_in, const int* in_sizes, int n_in,
                              void* d_out, int out_size) {
    const float* x     = (const float*)d_in[0];   // (128, 1024)
    const float* W     = (const float*)d_in[1];   // (512, 1024)
    const float* bias  = (const float*)d_in[2];   // (512,)
    const float* theta = (const float*)d_in[3];   // (512, 1024, 4)
    float* out = (float*)d_out;                   // (128, 512)

    (void)in_sizes; (void)n_in; (void)out_size;

    int n_weff = OUT_DIM * IN_DIM;
    weff_kernel<<<(n_weff + 255) / 256, 256>>>(W, theta);

    dim3 grid(OUT_DIM / OT, B_DIM / BT);   // (32, 8) = 256 blocks
    dim3 block(OT, BT);                    // 256 threads
    fbn_main_kernel<<<grid, block>>>(x, bias, out);
}

// round 2
// speedup vs baseline: 2.2402x; 2.2402x over previous
#include <cuda_runtime.h>

#define IN_DIM  1024
#define OUT_DIM 512
#define B_DIM   128
#define IC      64      // input-dim chunk staged in smem
#define OT      16      // output tile per block
#define BT      16      // batch tile per block
#define SPLITS  4
#define I_PER   (IN_DIM / SPLITS)   // 256 inputs per block

// Precomputed W_eff (plain; tanh.approx consumes z directly).
__device__ float g_w[OUT_DIM * IN_DIM];
// Partial sums: [split][b][o]
__device__ float g_part[SPLITS * B_DIM * OUT_DIM];

__device__ __forceinline__ float tanh_approx(float x) {
    float y;
    asm("tanh.approx.f32 %0, %1;" : "=f"(y) : "f"(x));
    return y;
}

// Kernel 1: W_eff[o,i] = softmax(theta[o,i,:]) . {0, W, tanh(W), sin(W)}
__global__ void weff_kernel(const float* __restrict__ W,
                            const float* __restrict__ theta) {
    int idx = blockIdx.x * blockDim.x + threadIdx.x;
    if (idx >= OUT_DIM * IN_DIM) return;
    float4 t = reinterpret_cast<const float4*>(theta)[idx];
    float m = fmaxf(fmaxf(t.x, t.y), fmaxf(t.z, t.w));
    float e0 = __expf(t.x - m);
    float e1 = __expf(t.y - m);
    float e2 = __expf(t.z - m);
    float e3 = __expf(t.w - m);
    float inv = __frcp_rn(e0 + e1 + e2 + e3);
    float w = W[idx];
    g_w[idx] = (e1 * w + e2 * tanh_approx(w) + e3 * __sinf(w)) * inv;
}

// Kernel 2: partial[s][b][o] = sum_{i in split s} tanh(x[b,i] * W_eff[o,i])
__global__ __launch_bounds__(OT * BT)
void fbn_main_kernel(const float* __restrict__ x) {
    __shared__ float xs[BT][IC + 4];   // stride 68 floats = 272B (16B aligned)
    __shared__ float ws[OT][IC + 4];

    const int tx = threadIdx.x;            // o within tile
    const int ty = threadIdx.y;            // b within tile
    const int o0 = blockIdx.x * OT;
    const int b0 = blockIdx.y * BT;
    const int c0 = blockIdx.z * I_PER;
    const int tid = ty * OT + tx;

    const int r = tid >> 4;                // staging row 0..15
    const int q = tid & 15;                // staging float4 col 0..15

    float acc0 = 0.0f, acc1 = 0.0f;

    for (int c = c0; c < c0 + I_PER; c += IC) {
        __syncthreads();
        // Stage 16x64 x-tile and 16x64 w-tile with float4 global loads.
        float4 xv = reinterpret_cast<const float4*>(x + (b0 + r) * IN_DIM + c)[q];
        *reinterpret_cast<float4*>(&xs[r][q * 4]) = xv;
        float4 wv = reinterpret_cast<const float4*>(g_w + (o0 + r) * IN_DIM + c)[q];
        *reinterpret_cast<float4*>(&ws[r][q * 4]) = wv;
        __syncthreads();

        #pragma unroll
        for (int i = 0; i < IC; i += 8) {
            float4 xa = *reinterpret_cast<const float4*>(&xs[ty][i]);
            float4 wa = *reinterpret_cast<const float4*>(&ws[tx][i]);
            float4 xb = *reinterpret_cast<const float4*>(&xs[ty][i + 4]);
            float4 wb = *reinterpret_cast<const float4*>(&ws[tx][i + 4]);
            acc0 += tanh_approx(xa.x * wa.x);
            acc1 += tanh_approx(xa.y * wa.y);
            acc0 += tanh_approx(xa.z * wa.z);
            acc1 += tanh_approx(xa.w * wa.w);
            acc0 += tanh_approx(xb.x * wb.x);
            acc1 += tanh_approx(xb.y * wb.y);
            acc0 += tanh_approx(xb.z * wb.z);
            acc1 += tanh_approx(xb.w * wb.w);
        }
    }

    g_part[(blockIdx.z * B_DIM + b0 + ty) * OUT_DIM + o0 + tx] = acc0 + acc1;
}

// Kernel 3: out[b][o] = bias[o] + sum_s partial[s][b][o]
__global__ void reduce_kernel(const float* __restrict__ bias,
                              float* __restrict__ out) {
    int idx = blockIdx.x * blockDim.x + threadIdx.x;   // 0..65535
    float s = bias[idx & (OUT_DIM - 1)];
    #pragma unroll
    for (int p = 0; p < SPLITS; p++)
        s += g_part[p * B_DIM * OUT_DIM + idx];
    out[idx] = s;
}

extern "C" void kernel_launch(void* const* d_in, const int* in_sizes, int n_in,
                              void* d_out, int out_size) {
    const float* x     = (const float*)d_in[0];   // (128, 1024)
    const float* W     = (const float*)d_in[1];   // (512, 1024)
    const float* bias  = (const float*)d_in[2];   // (512,)
    const float* theta = (const float*)d_in[3];   // (512, 1024, 4)
    float* out = (float*)d_out;                   // (128, 512)

    (void)in_sizes; (void)n_in; (void)out_size;

    int n_weff = OUT_DIM * IN_DIM;
    weff_kernel<<<(n_weff + 255) / 256, 256>>>(W, theta);

    dim3 grid(OUT_DIM / OT, B_DIM / BT, SPLITS);   // (32, 8, 4) = 1024 blocks
    dim3 block(OT, BT);                            // 256 threads
    fbn_main_kernel<<<grid, block>>>(x);

    reduce_kernel<<<(B_DIM * OUT_DIM) / 256, 256>>>(bias, out);
}

// round 3
// speedup vs baseline: 2.3784x; 1.0617x over previous
#include <cuda_runtime.h>

#define IN_DIM  1024
#define OUT_DIM 512
#define B_DIM   128
#define OT      16      // output tile per block
#define BT      16      // batch tile per block
#define SPLITS  4
#define I_PER   (IN_DIM / SPLITS)   // 256 inputs per block
#define LDW     (I_PER + 4)         // 260: 16B-aligned, conflict-free rows

// Precomputed W_eff (tanh.approx consumes z directly).
__device__ float g_w[OUT_DIM * IN_DIM];
// Partial sums: [split][b][o]
__device__ float g_part[SPLITS * B_DIM * OUT_DIM];

__device__ __forceinline__ float tanh_approx(float x) {
    float y;
    asm("tanh.approx.f32 %0, %1;" : "=f"(y) : "f"(x));
    return y;
}

// Kernel 1: W_eff[o,i] = softmax(theta[o,i,:]) . {0, W, tanh(W), sin(W)}
// 4 elements per thread, loads front-batched for MLP.
__global__ __launch_bounds__(256)
void weff_kernel(const float* __restrict__ W,
                 const float* __restrict__ theta) {
    int e0 = (blockIdx.x * blockDim.x + threadIdx.x) * 4;  // first element
    // Batch all global loads up front (MLP = 5 x LDG.128).
    float4 t0 = reinterpret_cast<const float4*>(theta)[e0 + 0];
    float4 t1 = reinterpret_cast<const float4*>(theta)[e0 + 1];
    float4 t2 = reinterpret_cast<const float4*>(theta)[e0 + 2];
    float4 t3 = reinterpret_cast<const float4*>(theta)[e0 + 3];
    float4 wv = *reinterpret_cast<const float4*>(W + e0);

    float4 r;
    {
        float a = __expf(t0.x), b = __expf(t0.y), c = __expf(t0.z), d = __expf(t0.w);
        float inv = __frcp_rn(a + b + c + d);
        r.x = (b * wv.x + c * tanh_approx(wv.x) + d * __sinf(wv.x)) * inv;
    }
    {
        float a = __expf(t1.x), b = __expf(t1.y), c = __expf(t1.z), d = __expf(t1.w);
        float inv = __frcp_rn(a + b + c + d);
        r.y = (b * wv.y + c * tanh_approx(wv.y) + d * __sinf(wv.y)) * inv;
    }
    {
        float a = __expf(t2.x), b = __expf(t2.y), c = __expf(t2.z), d = __expf(t2.w);
        float inv = __frcp_rn(a + b + c + d);
        r.z = (b * wv.z + c * tanh_approx(wv.z) + d * __sinf(wv.z)) * inv;
    }
    {
        float a = __expf(t3.x), b = __expf(t3.y), c = __expf(t3.z), d = __expf(t3.w);
        float inv = __frcp_rn(a + b + c + d);
        r.w = (b * wv.w + c * tanh_approx(wv.w) + d * __sinf(wv.w)) * inv;
    }
    *reinterpret_cast<float4*>(g_w + e0) = r;
}

// Kernel 2: partial[s][b][o] = sum_{i in split s} tanh(x[b,i] * W_eff[o,i])
// Full 256-wide split staged in smem once per block (2 syncs total).
__global__ __launch_bounds__(OT * BT)
void fbn_main_kernel(const float* __restrict__ x) {
    __shared__ float xs[BT][LDW];
    __shared__ float ws[OT][LDW];

    const int tx = threadIdx.x;            // o within tile
    const int ty = threadIdx.y;            // b within tile
    const int o0 = blockIdx.x * OT;
    const int b0 = blockIdx.y * BT;
    const int c0 = blockIdx.z * I_PER;
    const int tid = ty * OT + tx;

    const int r = tid >> 4;                // staging row 0..15
    const int q = tid & 15;                // staging float4 lane 0..15

    // Stage 16x256 x-tile and 16x256 w-tile: 8 LDG.128 per thread, batched.
    const float4* xg = reinterpret_cast<const float4*>(x   + (b0 + r) * IN_DIM + c0);
    const float4* wg = reinterpret_cast<const float4*>(g_w + (o0 + r) * IN_DIM + c0);
    float4 xv0 = xg[q];      float4 wv0 = wg[q];
    float4 xv1 = xg[q + 16]; float4 wv1 = wg[q + 16];
    float4 xv2 = xg[q + 32]; float4 wv2 = wg[q + 32];
    float4 xv3 = xg[q + 48]; float4 wv3 = wg[q + 48];
    *reinterpret_cast<float4*>(&xs[r][(q     ) * 4]) = xv0;
    *reinterpret_cast<float4*>(&ws[r][(q     ) * 4]) = wv0;
    *reinterpret_cast<float4*>(&xs[r][(q + 16) * 4]) = xv1;
    *reinterpret_cast<float4*>(&ws[r][(q + 16) * 4]) = wv1;
    *reinterpret_cast<float4*>(&xs[r][(q + 32) * 4]) = xv2;
    *reinterpret_cast<float4*>(&ws[r][(q + 32) * 4]) = wv2;
    *reinterpret_cast<float4*>(&xs[r][(q + 48) * 4]) = xv3;
    *reinterpret_cast<float4*>(&ws[r][(q + 48) * 4]) = wv3;
    __syncthreads();

    float acc0 = 0.0f, acc1 = 0.0f;
    #pragma unroll
    for (int i = 0; i < I_PER; i += 8) {
        float4 xa = *reinterpret_cast<const float4*>(&xs[ty][i]);
        float4 wa = *reinterpret_cast<const float4*>(&ws[tx][i]);
        float4 xb = *reinterpret_cast<const float4*>(&xs[ty][i + 4]);
        float4 wb = *reinterpret_cast<const float4*>(&ws[tx][i + 4]);
        acc0 += tanh_approx(xa.x * wa.x);
        acc1 += tanh_approx(xa.y * wa.y);
        acc0 += tanh_approx(xa.z * wa.z);
        acc1 += tanh_approx(xa.w * wa.w);
        acc0 += tanh_approx(xb.x * wb.x);
        acc1 += tanh_approx(xb.y * wb.y);
        acc0 += tanh_approx(xb.z * wb.z);
        acc1 += tanh_approx(xb.w * wb.w);
    }

    g_part[(blockIdx.z * B_DIM + b0 + ty) * OUT_DIM + o0 + tx] = acc0 + acc1;
}

// Kernel 3: out[b][o] = bias[o] + sum_s partial[s][b][o]
__global__ void reduce_kernel(const float* __restrict__ bias,
                              float* __restrict__ out) {
    int idx = blockIdx.x * blockDim.x + threadIdx.x;   // 0..65535
    float s = bias[idx & (OUT_DIM - 1)];
    #pragma unroll
    for (int p = 0; p < SPLITS; p++)
        s += g_part[p * B_DIM * OUT_DIM + idx];
    out[idx] = s;
}

extern "C" void kernel_launch(void* const* d_in, const int* in_sizes, int n_in,
                              void* d_out, int out_size) {
    const float* x     = (const float*)d_in[0];   // (128, 1024)
    const float* W     = (const float*)d_in[1];   // (512, 1024)
    const float* bias  = (const float*)d_in[2];   // (512,)
    const float* theta = (const float*)d_in[3];   // (512, 1024, 4)
    float* out = (float*)d_out;                   // (128, 512)

    (void)in_sizes; (void)n_in; (void)out_size;

    // 512K elements / 4 per thread / 256 per block = 512 blocks
    weff_kernel<<<(OUT_DIM * IN_DIM) / (4 * 256), 256>>>(W, theta);

    dim3 grid(OUT_DIM / OT, B_DIM / BT, SPLITS);   // (32, 8, 4) = 1024 blocks
    dim3 block(OT, BT);                            // 256 threads
    fbn_main_kernel<<<grid, block>>>(x);

    reduce_kernel<<<(B_DIM * OUT_DIM) / 256, 256>>>(bias, out);
}